// round 9
// baseline (speedup 1.0000x reference)
#include <cuda_runtime.h>
#include <cuda_bf16.h>
#include <cstdint>

// Problem constants (fixed by the dataset)
#define BB 512      // batch
#define TT 512      // timesteps
#define II 128      // sensory inputs
#define UU 64       // LTC units
#define OO 15       // outputs
#define NUNF 4      // ode unfolds
#define LTC_EPS 1e-8f

// ---------------- device scratch (allocation-free rule: __device__ globals) ---------
__device__ float4 g_sparam[II * UU];     // sensory per-synapse {a, b, ce, c}
__device__ float4 g_rparam[UU * UU];     // recurrent per-synapse {a, b, ce, c}
__device__ float  g_sKn[UU], g_sKd[UU];  // sensory constant sums
__device__ float  g_cmt[UU], g_numbase[UU], g_denbase[UU];
__device__ float2 g_wns[BB * TT * UU];   // (w_num_s, w_den_s) per (b,t,u)  ~134MB

// ---------------- helpers ------------------------------------------------------------
// Two tanh for one MUFU op: pack two f32 args into f16x2, tanh.approx.f16x2, unpack.
__device__ __forceinline__ void tanh2_fast(float ax, float ay, float& tx, float& ty) {
    uint32_t h, r;
    asm("cvt.rn.f16x2.f32 %0, %1, %2;" : "=r"(h) : "f"(ay), "f"(ax));
    asm("tanh.approx.f16x2 %0, %1;" : "=r"(r) : "r"(h));
    asm("{\n\t"
        ".reg .b16 lo, hi;\n\t"
        "mov.b32 {lo, hi}, %2;\n\t"
        "cvt.f32.f16 %0, lo;\n\t"
        "cvt.f32.f16 %1, hi;\n\t"
        "}" : "=f"(tx), "=f"(ty) : "r"(r));
}
__device__ __forceinline__ float softplus_f(float x) {
    return log1pf(expf(x));
}

// ---------------- kernel 0a: fold parameters (one thread per synapse) -----------------
__global__ void fold_params_kernel(
    const float* __restrict__ iw, const float* __restrict__ ib,
    const float* __restrict__ sw, const float* __restrict__ smu,
    const float* __restrict__ ssig, const float* __restrict__ serev,
    const float* __restrict__ w, const float* __restrict__ mu,
    const float* __restrict__ sig, const float* __restrict__ erev)
{
    int idx = blockIdx.x * blockDim.x + threadIdx.x;
    if (idx < II * UU) {
        int i = idx / UU;
        float c  = 0.5f * softplus_f(sw[idx]);
        float ce = c * serev[idx];
        float a  = 0.5f * ssig[idx] * iw[i];
        float b  = 0.5f * ssig[idx] * (ib[i] - smu[idx]);
        g_sparam[idx] = make_float4(a, b, ce, c);
    }
    int r = idx - II * UU;
    if (r >= 0 && r < UU * UU) {
        float c  = 0.5f * softplus_f(w[r]);
        float ce = c * erev[r];
        float a  = 0.5f * sig[r];
        float b  = -0.5f * sig[r] * mu[r];
        g_rparam[r] = make_float4(a, b, ce, c);
    }
}

// ---------------- kernel 0b: per-neuron constant sums ---------------------------------
__global__ void fold_neuron_kernel(
    const float* __restrict__ gleak, const float* __restrict__ vleak,
    const float* __restrict__ cm)
{
    int u = threadIdx.x;
    if (u >= UU) return;

    float kn = 0.f, kd = 0.f;
#pragma unroll 8
    for (int i = 0; i < II; i++) {
        float4 p = g_sparam[i * UU + u];
        kn += p.z; kd += p.w;
    }
    g_sKn[u] = kn;
    g_sKd[u] = kd;

    kn = 0.f; kd = 0.f;
#pragma unroll 8
    for (int j = 0; j < UU; j++) {
        float4 p = g_rparam[j * UU + u];
        kn += p.z; kd += p.w;
    }
    float gp  = softplus_f(gleak[u]);
    float cmt = (float)NUNF * softplus_f(cm[u]);   // sp(cm) / (1/UNFOLDS)
    g_cmt[u]     = cmt;
    g_numbase[u] = gp * vleak[u] + kn;
    g_denbase[u] = cmt + gp + kd + LTC_EPS;
}

// ---------------- kernel 1: sensory synapse sums over all (b,t) ----------------------
// Barrier-free, no smem. 512 threads: u = tid>>3, ig = tid&7 (8 groups of 16 inputs).
// Two rows per iteration; the (row0,row1) tanh pair shares one tanh.approx.f16x2.
#define ROWS_PER_BLOCK 128
__global__ __launch_bounds__(512, 1) void sensory_kernel(const float* __restrict__ x)
{
    const int tid = threadIdx.x;
    const int u  = tid >> 3;
    const int ig = tid & 7;

    float pa[16], pb[16], pce[16];
#pragma unroll
    for (int ii = 0; ii < 16; ii++) {
        float4 p = g_sparam[(ig * 16 + ii) * UU + u];
        pa[ii] = p.x; pb[ii] = p.y; pce[ii] = p.z;
    }
    const float kn = g_sKn[u];
    const float kd = g_sKd[u];

    const size_t base_row = (size_t)blockIdx.x * ROWS_PER_BLOCK;
    const float4* __restrict__ xr = (const float4*)x + base_row * (II / 4) + ig * 4;

    for (int r = 0; r < ROWS_PER_BLOCK; r += 2) {
        float4 x0[4], x1[4];
#pragma unroll
        for (int q = 0; q < 4; q++) {
            x0[q] = xr[(size_t)r * (II / 4) + q];
            x1[q] = xr[(size_t)(r + 1) * (II / 4) + q];
        }

        float pn0 = 0.f, pd0 = 0.f, pn1 = 0.f, pd1 = 0.f;
#pragma unroll
        for (int q = 0; q < 4; q++) {
            const int s = q * 4;
            const float xv0[4] = {x0[q].x, x0[q].y, x0[q].z, x0[q].w};
            const float xv1[4] = {x1[q].x, x1[q].y, x1[q].z, x1[q].w};
#pragma unroll
            for (int e = 0; e < 4; e++) {
                float a0 = fmaf(pa[s + e], xv0[e], pb[s + e]);
                float a1 = fmaf(pa[s + e], xv1[e], pb[s + e]);
                float t0, t1;
                tanh2_fast(a0, a1, t0, t1);
                float ce = pce[s + e];
                float c  = fabsf(ce);
                pn0 = fmaf(ce, t0, pn0);  pd0 = fmaf(c, t0, pd0);
                pn1 = fmaf(ce, t1, pn1);  pd1 = fmaf(c, t1, pd1);
            }
        }
#pragma unroll
        for (int o = 1; o <= 4; o <<= 1) {
            pn0 += __shfl_xor_sync(0xffffffffu, pn0, o);
            pn1 += __shfl_xor_sync(0xffffffffu, pn1, o);
            pd0 += __shfl_xor_sync(0xffffffffu, pd0, o);
            pd1 += __shfl_xor_sync(0xffffffffu, pd1, o);
        }
        if (ig == 0) {
            __stcg(&g_wns[(base_row + r) * UU + u],     make_float2(pn0 + kn, pd0 + kd));
            __stcg(&g_wns[(base_row + r + 1) * UU + u], make_float2(pn1 + kn, pd1 + kd));
        }
    }
}

// ---------------- kernel 2: sequential scan + LayerNorm + FC head --------------------
// grid=256, block=256 (8 warps). Thread (u = tid>>2, qg = tid&3) owns 16 of unit u's
// recurrent synapses (48 param regs) for TWO batches. __launch_bounds__(256,2) caps
// regs at 128 -> 2 blocks/SM -> 4 warps/SMSP from independent barrier domains.
// Quarter combine: shfl_xor(1), shfl_xor(2); all lanes divide redundantly.
__global__ __launch_bounds__(256, 2) void scan_kernel(
    const float* __restrict__ outw, const float* __restrict__ outb,
    const float* __restrict__ lnw,  const float* __restrict__ lnb,
    const float* __restrict__ fcw,  const float* __restrict__ fcb,
    float* __restrict__ out)
{
    __shared__ float vsm[2][2][UU];     // [batch][buffer][unit]
    __shared__ float hbuf[2][UU];
    __shared__ float stats[2][2];

    const int tid = threadIdx.x;
    const int u   = tid >> 2;           // 0..63
    const int qg  = tid & 3;            // quarter: which 16 synapses of unit u
    const int bA  = blockIdx.x * 2;
    const int bB  = bA + 1;

    float pa[16], pb[16], pce[16];
#pragma unroll
    for (int j = 0; j < 16; j++) {
        float4 p = g_rparam[(qg * 16 + j) * UU + u];
        pa[j] = p.x; pb[j] = p.y; pce[j] = p.z;
    }
    const float cmtu = g_cmt[u];
    const float nb   = g_numbase[u];
    const float db   = g_denbase[u];

    if (tid < UU) {
        vsm[0][0][tid] = 0.f;
        vsm[1][0][tid] = 0.f;
    }
    float vA = 0.f, vB = 0.f;
    __syncthreads();

    const float2* __restrict__ wnsA = g_wns + (size_t)bA * TT * UU;
    const float2* __restrict__ wnsB = g_wns + (size_t)bB * TT * UU;
    float2 wndA = __ldcg(&wnsA[u]);
    float2 wndB = __ldcg(&wnsB[u]);

    for (int t = 0; t < TT; t++) {
        float2 wndA_n, wndB_n;
        if (t + 1 < TT) {
            wndA_n = __ldcg(&wnsA[(t + 1) * UU + u]);
            wndB_n = __ldcg(&wnsB[(t + 1) * UU + u]);
        } else {
            wndA_n = make_float2(0.f, 0.f);
            wndB_n = make_float2(0.f, 0.f);
        }
#pragma unroll
        for (int k = 0; k < NUNF; k++) {
            const int cur = k & 1, nxt = cur ^ 1;
            const float4* vrA = (const float4*)(vsm[0][cur]) + qg * 4;
            const float4* vrB = (const float4*)(vsm[1][cur]) + qg * 4;

            // split accumulator chains (even/odd q) for ILP
            float pnA0 = 0.f, pdA0 = 0.f, pnB0 = 0.f, pdB0 = 0.f;
            float pnA1 = 0.f, pdA1 = 0.f, pnB1 = 0.f, pdB1 = 0.f;
#pragma unroll
            for (int q = 0; q < 4; q++) {
                float4 a4 = vrA[q];
                float4 b4 = vrB[q];
                const int s = q * 4;
                const float va[4] = {a4.x, a4.y, a4.z, a4.w};
                const float vb[4] = {b4.x, b4.y, b4.z, b4.w};
#pragma unroll
                for (int e = 0; e < 4; e++) {
                    float aA = fmaf(pa[s + e], va[e], pb[s + e]);
                    float aB = fmaf(pa[s + e], vb[e], pb[s + e]);
                    float tA, tB;
                    tanh2_fast(aA, aB, tA, tB);
                    float ce = pce[s + e];
                    float c  = fabsf(ce);
                    if (q & 1) {
                        pnA1 = fmaf(ce, tA, pnA1);  pdA1 = fmaf(c, tA, pdA1);
                        pnB1 = fmaf(ce, tB, pnB1);  pdB1 = fmaf(c, tB, pdB1);
                    } else {
                        pnA0 = fmaf(ce, tA, pnA0);  pdA0 = fmaf(c, tA, pdA0);
                        pnB0 = fmaf(ce, tB, pnB0);  pdB0 = fmaf(c, tB, pdB0);
                    }
                }
            }
            float pnA = pnA0 + pnA1, pdA = pdA0 + pdA1;
            float pnB = pnB0 + pnB1, pdB = pdB0 + pdB1;

            // combine the 4 quarters (adjacent lanes: xor 1, xor 2)
#pragma unroll
            for (int o = 1; o <= 2; o <<= 1) {
                pnA += __shfl_xor_sync(0xffffffffu, pnA, o);
                pdA += __shfl_xor_sync(0xffffffffu, pdA, o);
                pnB += __shfl_xor_sync(0xffffffffu, pnB, o);
                pdB += __shfl_xor_sync(0xffffffffu, pdB, o);
            }

            vA = __fdividef(fmaf(cmtu, vA, nb) + wndA.x + pnA, db + wndA.y + pdA);
            vB = __fdividef(fmaf(cmtu, vB, nb) + wndB.x + pnB, db + wndB.y + pdB);
            if (qg == 0) {
                vsm[0][nxt][u] = vA;
                vsm[1][nxt][u] = vB;
            }
            __syncthreads();
        }
        wndA = wndA_n;
        wndB = wndB_n;
    }

    // ----- head: per batch: h = v*ow + ob; LayerNorm(eps=1e-5); FC -----
    if (qg == 0) {
        float ow = outw[u], ob = outb[u];
        hbuf[0][u] = fmaf(vA, ow, ob);
        hbuf[1][u] = fmaf(vB, ow, ob);
    }
    __syncthreads();
    {
        const int wid  = tid >> 5;
        const int lane = tid & 31;
        if (wid < 2) {                        // warp 0 -> batch A, warp 1 -> batch B
            float h0 = hbuf[wid][lane], h1 = hbuf[wid][lane + 32];
            float a = h0 + h1;
            float q = h0 * h0 + h1 * h1;
#pragma unroll
            for (int o = 16; o > 0; o >>= 1) {
                a += __shfl_down_sync(0xffffffffu, a, o);
                q += __shfl_down_sync(0xffffffffu, q, o);
            }
            if (lane == 0) {
                float mean = a * (1.0f / UU);
                float var  = q * (1.0f / UU) - mean * mean;
                stats[wid][0] = mean;
                stats[wid][1] = rsqrtf(var + 1e-5f);
            }
            __syncwarp();
            float mean = stats[wid][0], rstd = stats[wid][1];
            hbuf[wid][lane]      = fmaf((h0 - mean) * rstd, lnw[lane],      lnb[lane]);
            hbuf[wid][lane + 32] = fmaf((h1 - mean) * rstd, lnw[lane + 32], lnb[lane + 32]);
            __syncwarp();
            if (lane < OO) {
                float acc = fcb[lane];
#pragma unroll
                for (int uu = 0; uu < UU; uu++)
                    acc = fmaf(hbuf[wid][uu], fcw[lane * UU + uu], acc);
                out[(blockIdx.x * 2 + wid) * OO + lane] = acc;
            }
        }
    }
}

// ---------------- launch --------------------------------------------------------------
extern "C" void kernel_launch(void* const* d_in, const int* in_sizes, int n_in,
                              void* d_out, int out_size)
{
    const float* x     = (const float*)d_in[0];
    const float* iw    = (const float*)d_in[1];
    const float* ibv   = (const float*)d_in[2];
    const float* sw    = (const float*)d_in[3];
    const float* smu   = (const float*)d_in[4];
    const float* ssig  = (const float*)d_in[5];
    const float* serev = (const float*)d_in[6];
    const float* w     = (const float*)d_in[7];
    const float* mu    = (const float*)d_in[8];
    const float* sig   = (const float*)d_in[9];
    const float* erev  = (const float*)d_in[10];
    const float* gleak = (const float*)d_in[11];
    const float* vleak = (const float*)d_in[12];
    const float* cm    = (const float*)d_in[13];
    const float* outw  = (const float*)d_in[14];
    const float* outb  = (const float*)d_in[15];
    const float* lnw   = (const float*)d_in[16];
    const float* lnb   = (const float*)d_in[17];
    const float* fcw   = (const float*)d_in[18];
    const float* fcb   = (const float*)d_in[19];
    float* out = (float*)d_out;

    const int n_syn = II * UU + UU * UU;           // 12288
    fold_params_kernel<<<(n_syn + 255) / 256, 256>>>(iw, ibv, sw, smu, ssig, serev,
                                                     w, mu, sig, erev);
    fold_neuron_kernel<<<1, 64>>>(gleak, vleak, cm);

    int nblocks = (BB * TT) / ROWS_PER_BLOCK;      // 2048
    sensory_kernel<<<nblocks, 512>>>(x);

    scan_kernel<<<BB / 2, 256>>>(outw, outb, lnw, lnb, fcw, fcb, out);
}

// round 10
// speedup vs baseline: 1.7690x; 1.7690x over previous
#include <cuda_runtime.h>
#include <cuda_bf16.h>
#include <cstdint>

// Problem constants (fixed by the dataset)
#define BB 512      // batch
#define TT 512      // timesteps
#define II 128      // sensory inputs
#define UU 64       // LTC units
#define OO 15       // outputs
#define NUNF 4      // ode unfolds
#define LTC_EPS 1e-8f

// ---------------- device scratch (allocation-free rule: __device__ globals) ---------
__device__ float4 g_sparam[II * UU];     // sensory per-synapse {a, b, ce, c}
__device__ float4 g_rparam[UU * UU];     // recurrent per-synapse {a, b, ce, c}
__device__ float  g_sKn[UU], g_sKd[UU];  // sensory constant sums
__device__ float  g_cmt[UU], g_numbase[UU], g_denbase[UU];
__device__ float2 g_wns[BB * TT * UU];   // (w_num_s, w_den_s) per (b,t,u)  ~134MB

// ---------------- packed f32x2 helpers ------------------------------------------------
__device__ __forceinline__ uint64_t pack_f32x2(float lo, float hi) {
    uint64_t r;
    asm("mov.b64 %0, {%1, %2};" : "=l"(r) : "f"(lo), "f"(hi));
    return r;
}
__device__ __forceinline__ float hadd_f32x2(uint64_t v) {
    float lo, hi;
    asm("mov.b64 {%0, %1}, %2;" : "=f"(lo), "=f"(hi) : "l"(v));
    return lo + hi;
}
// One packed step for 2 synapses: arg = a*v+b (FFMA2); tanh via f16x2 (1 MUFU);
// pn += ce*t, pd += c*t (FFMA2 each).
__device__ __forceinline__ void syn2_step(uint64_t a2, uint64_t b2, uint64_t ce2,
                                          uint64_t c2, uint64_t v2,
                                          uint64_t& pn2, uint64_t& pd2) {
    uint64_t arg2, t2;
    asm("fma.rn.f32x2 %0, %1, %2, %3;" : "=l"(arg2) : "l"(a2), "l"(v2), "l"(b2));
    float alo, ahi;
    asm("mov.b64 {%0, %1}, %2;" : "=f"(alo), "=f"(ahi) : "l"(arg2));
    uint32_t h, r;
    asm("cvt.rn.f16x2.f32 %0, %1, %2;" : "=r"(h) : "f"(ahi), "f"(alo)); // 1st->high half
    asm("tanh.approx.f16x2 %0, %1;" : "=r"(r) : "r"(h));
    float tlo, thi;
    asm("{\n\t"
        ".reg .b16 lo16, hi16;\n\t"
        "mov.b32 {lo16, hi16}, %2;\n\t"
        "cvt.f32.f16 %0, lo16;\n\t"
        "cvt.f32.f16 %1, hi16;\n\t"
        "}" : "=f"(tlo), "=f"(thi) : "r"(r));
    asm("mov.b64 %0, {%1, %2};" : "=l"(t2) : "f"(tlo), "f"(thi));
    asm("fma.rn.f32x2 %0, %1, %2, %0;" : "+l"(pn2) : "l"(ce2), "l"(t2));
    asm("fma.rn.f32x2 %0, %1, %2, %0;" : "+l"(pd2) : "l"(c2), "l"(t2));
}
__device__ __forceinline__ float softplus_f(float x) {
    return log1pf(expf(x));
}

// ---------------- kernel 0a: fold parameters (one thread per synapse) -----------------
// sigmoid(z) = 0.5*tanh(z/2)+0.5; a = 0.5*sigma*iw, b = 0.5*sigma*(ib-mu),
// c = 0.5*sp(w), ce = c*erev (erev = +-1 so c == |ce|).
__global__ void fold_params_kernel(
    const float* __restrict__ iw, const float* __restrict__ ib,
    const float* __restrict__ sw, const float* __restrict__ smu,
    const float* __restrict__ ssig, const float* __restrict__ serev,
    const float* __restrict__ w, const float* __restrict__ mu,
    const float* __restrict__ sig, const float* __restrict__ erev)
{
    int idx = blockIdx.x * blockDim.x + threadIdx.x;
    if (idx < II * UU) {
        int i = idx / UU;
        float c  = 0.5f * softplus_f(sw[idx]);
        float ce = c * serev[idx];
        float a  = 0.5f * ssig[idx] * iw[i];
        float b  = 0.5f * ssig[idx] * (ib[i] - smu[idx]);
        g_sparam[idx] = make_float4(a, b, ce, c);
    }
    int r = idx - II * UU;
    if (r >= 0 && r < UU * UU) {
        float c  = 0.5f * softplus_f(w[r]);
        float ce = c * erev[r];
        float a  = 0.5f * sig[r];
        float b  = -0.5f * sig[r] * mu[r];
        g_rparam[r] = make_float4(a, b, ce, c);
    }
}

// ---------------- kernel 0b: per-neuron constant sums (parallel, 256 threads) ---------
__global__ void fold_neuron_kernel(
    const float* __restrict__ gleak, const float* __restrict__ vleak,
    const float* __restrict__ cm)
{
    __shared__ float part[4][4][UU];
    const int tid = threadIdx.x;
    const int u = tid & 63;
    const int g = tid >> 6;

    float skn = 0.f, skd = 0.f;
#pragma unroll 4
    for (int i = g * 32; i < g * 32 + 32; i++) {
        float4 p = g_sparam[i * UU + u];
        skn += p.z; skd += p.w;
    }
    float rkn = 0.f, rkd = 0.f;
#pragma unroll 4
    for (int j = g * 16; j < g * 16 + 16; j++) {
        float4 p = g_rparam[j * UU + u];
        rkn += p.z; rkd += p.w;
    }
    part[g][0][u] = skn; part[g][1][u] = skd;
    part[g][2][u] = rkn; part[g][3][u] = rkd;
    __syncthreads();
    if (g == 0) {
        skn = part[0][0][u] + part[1][0][u] + part[2][0][u] + part[3][0][u];
        skd = part[0][1][u] + part[1][1][u] + part[2][1][u] + part[3][1][u];
        rkn = part[0][2][u] + part[1][2][u] + part[2][2][u] + part[3][2][u];
        rkd = part[0][3][u] + part[1][3][u] + part[2][3][u] + part[3][3][u];
        g_sKn[u] = skn;
        g_sKd[u] = skd;
        float gp  = softplus_f(gleak[u]);
        float cmt = (float)NUNF * softplus_f(cm[u]);
        g_cmt[u]     = cmt;
        g_numbase[u] = gp * vleak[u] + rkn;
        g_denbase[u] = cmt + gp + rkd + LTC_EPS;
    }
}

// ---------------- kernel 1: sensory synapse sums over all (b,t) ----------------------
// Barrier-free, no smem. 512 threads: u = tid>>3, ig = tid&7 (16 inputs each = 8 pairs).
// Synapse pairs (i,i+1) packed f32x2; x pairs come free from ulonglong2 loads
// (16 floats = 8 uint64 pairs = 4 ulonglong2 per row per thread).
#define ROWS_PER_BLOCK 128
__global__ __launch_bounds__(512, 1) void sensory_kernel(const float* __restrict__ x)
{
    const int tid = threadIdx.x;
    const int u  = tid >> 3;
    const int ig = tid & 7;

    uint64_t a2[8], b2[8], ce2[8], c2[8];
#pragma unroll
    for (int p = 0; p < 8; p++) {
        int i = ig * 16 + p * 2;
        float4 q0 = g_sparam[i * UU + u];
        float4 q1 = g_sparam[(i + 1) * UU + u];
        a2[p]  = pack_f32x2(q0.x, q1.x);
        b2[p]  = pack_f32x2(q0.y, q1.y);
        ce2[p] = pack_f32x2(q0.z, q1.z);
        c2[p]  = pack_f32x2(q0.w, q1.w);
    }
    const float kn = g_sKn[u];
    const float kd = g_sKd[u];

    const size_t base_row = (size_t)blockIdx.x * ROWS_PER_BLOCK;
    // row stride in ulonglong2 units = II/4 = 32? No: II floats = II/2 pairs = II/4 u2 = 32.
    const ulonglong2* __restrict__ xr =
        reinterpret_cast<const ulonglong2*>(x + base_row * II) + ig * 4;
    const int ROWSTRIDE = II / 4;   // 32 ulonglong2 per row

    for (int r = 0; r < ROWS_PER_BLOCK; r += 2) {
        ulonglong2 x0[4], x1[4];
#pragma unroll
        for (int q = 0; q < 4; q++) {
            x0[q] = xr[(size_t)r * ROWSTRIDE + q];
            x1[q] = xr[(size_t)(r + 1) * ROWSTRIDE + q];
        }

        uint64_t pn0 = 0ull, pd0 = 0ull, pn1 = 0ull, pd1 = 0ull;
#pragma unroll
        for (int q = 0; q < 4; q++) {
            syn2_step(a2[q * 2 + 0], b2[q * 2 + 0], ce2[q * 2 + 0], c2[q * 2 + 0], x0[q].x, pn0, pd0);
            syn2_step(a2[q * 2 + 1], b2[q * 2 + 1], ce2[q * 2 + 1], c2[q * 2 + 1], x0[q].y, pn0, pd0);
            syn2_step(a2[q * 2 + 0], b2[q * 2 + 0], ce2[q * 2 + 0], c2[q * 2 + 0], x1[q].x, pn1, pd1);
            syn2_step(a2[q * 2 + 1], b2[q * 2 + 1], ce2[q * 2 + 1], c2[q * 2 + 1], x1[q].y, pn1, pd1);
        }

        float spn0 = hadd_f32x2(pn0), spd0 = hadd_f32x2(pd0);
        float spn1 = hadd_f32x2(pn1), spd1 = hadd_f32x2(pd1);
#pragma unroll
        for (int o = 1; o <= 4; o <<= 1) {
            spn0 += __shfl_xor_sync(0xffffffffu, spn0, o);
            spn1 += __shfl_xor_sync(0xffffffffu, spn1, o);
            spd0 += __shfl_xor_sync(0xffffffffu, spd0, o);
            spd1 += __shfl_xor_sync(0xffffffffu, spd1, o);
        }
        if (ig == 0) {
            __stcg(&g_wns[(base_row + r) * UU + u],     make_float2(spn0 + kn, spd0 + kd));
            __stcg(&g_wns[(base_row + r + 1) * UU + u], make_float2(spn1 + kn, spd1 + kd));
        }
    }
}

// ---------------- kernel 2: sequential scan + LayerNorm + FC head --------------------
// grid=256, block=128. Thread (u=tid>>1, half=tid&1) owns 32 synapses of unit u as
// 16 packed f32x2 pairs (params in registers), processes 2 batches. v pairs come
// free from ulonglong2 shared loads. One shfl_xor(1) per batch; redundant division.
__global__ __launch_bounds__(128, 2) void scan_kernel(
    const float* __restrict__ outw, const float* __restrict__ outb,
    const float* __restrict__ lnw,  const float* __restrict__ lnb,
    const float* __restrict__ fcw,  const float* __restrict__ fcb,
    float* __restrict__ out)
{
    __shared__ alignas(16) float vsm[2][2][UU];   // [batch][buffer][unit]
    __shared__ float hbuf[2][UU];
    __shared__ float stats[2][2];

    const int tid  = threadIdx.x;
    const int u    = tid >> 1;
    const int half = tid & 1;
    const int bA   = blockIdx.x * 2;
    const int bB   = bA + 1;

    uint64_t a2[16], b2[16], ce2[16], c2[16];
#pragma unroll
    for (int p = 0; p < 16; p++) {
        int j = half * 32 + p * 2;
        float4 q0 = g_rparam[j * UU + u];
        float4 q1 = g_rparam[(j + 1) * UU + u];
        a2[p]  = pack_f32x2(q0.x, q1.x);
        b2[p]  = pack_f32x2(q0.y, q1.y);
        ce2[p] = pack_f32x2(q0.z, q1.z);
        c2[p]  = pack_f32x2(q0.w, q1.w);
    }
    const float cmtu = g_cmt[u];
    const float nb   = g_numbase[u];
    const float db   = g_denbase[u];

    if (half == 0) {
        vsm[0][0][u] = 0.f;
        vsm[1][0][u] = 0.f;
    }
    float vA = 0.f, vB = 0.f;
    __syncthreads();

    const float2* __restrict__ wnsA = g_wns + (size_t)bA * TT * UU;
    const float2* __restrict__ wnsB = g_wns + (size_t)bB * TT * UU;
    float2 wndA = __ldcg(&wnsA[u]);
    float2 wndB = __ldcg(&wnsB[u]);

    for (int t = 0; t < TT; t++) {
        float2 wndA_n, wndB_n;
        if (t + 1 < TT) {
            wndA_n = __ldcg(&wnsA[(t + 1) * UU + u]);
            wndB_n = __ldcg(&wnsB[(t + 1) * UU + u]);
        } else {
            wndA_n = make_float2(0.f, 0.f);
            wndB_n = make_float2(0.f, 0.f);
        }
#pragma unroll
        for (int k = 0; k < NUNF; k++) {
            const int cur = k & 1, nxt = cur ^ 1;
            const ulonglong2* vrA =
                reinterpret_cast<const ulonglong2*>(&vsm[0][cur][half * 32]);
            const ulonglong2* vrB =
                reinterpret_cast<const ulonglong2*>(&vsm[1][cur][half * 32]);

            uint64_t pnA = 0ull, pdA = 0ull, pnB = 0ull, pdB = 0ull;
#pragma unroll
            for (int q = 0; q < 8; q++) {            // 8 ulonglong2 = 16 pairs = 32 syn
                ulonglong2 va = vrA[q];
                ulonglong2 vb = vrB[q];
                syn2_step(a2[q * 2 + 0], b2[q * 2 + 0], ce2[q * 2 + 0], c2[q * 2 + 0], va.x, pnA, pdA);
                syn2_step(a2[q * 2 + 1], b2[q * 2 + 1], ce2[q * 2 + 1], c2[q * 2 + 1], va.y, pnA, pdA);
                syn2_step(a2[q * 2 + 0], b2[q * 2 + 0], ce2[q * 2 + 0], c2[q * 2 + 0], vb.x, pnB, pdB);
                syn2_step(a2[q * 2 + 1], b2[q * 2 + 1], ce2[q * 2 + 1], c2[q * 2 + 1], vb.y, pnB, pdB);
            }
            float spnA = hadd_f32x2(pnA), spdA = hadd_f32x2(pdA);
            float spnB = hadd_f32x2(pnB), spdB = hadd_f32x2(pdB);
            spnA += __shfl_xor_sync(0xffffffffu, spnA, 1);
            spdA += __shfl_xor_sync(0xffffffffu, spdA, 1);
            spnB += __shfl_xor_sync(0xffffffffu, spnB, 1);
            spdB += __shfl_xor_sync(0xffffffffu, spdB, 1);

            vA = __fdividef(fmaf(cmtu, vA, nb) + wndA.x + spnA, db + wndA.y + spdA);
            vB = __fdividef(fmaf(cmtu, vB, nb) + wndB.x + spnB, db + wndB.y + spdB);
            if (half == 0) {
                vsm[0][nxt][u] = vA;
                vsm[1][nxt][u] = vB;
            }
            __syncthreads();
        }
        wndA = wndA_n;
        wndB = wndB_n;
    }

    // ----- head: per batch: h = v*ow + ob; LayerNorm(eps=1e-5); FC -----
    if (half == 0) {
        float ow = outw[u], ob = outb[u];
        hbuf[0][u] = fmaf(vA, ow, ob);
        hbuf[1][u] = fmaf(vB, ow, ob);
    }
    __syncthreads();
    {
        const int wid  = tid >> 5;
        const int lane = tid & 31;
        if ((wid & 1) == 0) {                 // warps 0,2 reduce batches 0,1
            const int s = wid >> 1;
            float h0 = hbuf[s][lane], h1 = hbuf[s][lane + 32];
            float a = h0 + h1;
            float q = h0 * h0 + h1 * h1;
#pragma unroll
            for (int o = 16; o > 0; o >>= 1) {
                a += __shfl_down_sync(0xffffffffu, a, o);
                q += __shfl_down_sync(0xffffffffu, q, o);
            }
            if (lane == 0) {
                float mean = a * (1.0f / UU);
                float var  = q * (1.0f / UU) - mean * mean;
                stats[s][0] = mean;
                stats[s][1] = rsqrtf(var + 1e-5f);
            }
            __syncwarp();
            float mean = stats[s][0], rstd = stats[s][1];
            hbuf[s][lane]      = fmaf((h0 - mean) * rstd, lnw[lane],      lnb[lane]);
            hbuf[s][lane + 32] = fmaf((h1 - mean) * rstd, lnw[lane + 32], lnb[lane + 32]);
            __syncwarp();
            if (lane < OO) {
                float acc = fcb[lane];
#pragma unroll
                for (int uu = 0; uu < UU; uu++)
                    acc = fmaf(hbuf[s][uu], fcw[lane * UU + uu], acc);
                out[(blockIdx.x * 2 + s) * OO + lane] = acc;
            }
        }
    }
}

// ---------------- launch --------------------------------------------------------------
extern "C" void kernel_launch(void* const* d_in, const int* in_sizes, int n_in,
                              void* d_out, int out_size)
{
    const float* x     = (const float*)d_in[0];
    const float* iw    = (const float*)d_in[1];
    const float* ibv   = (const float*)d_in[2];
    const float* sw    = (const float*)d_in[3];
    const float* smu   = (const float*)d_in[4];
    const float* ssig  = (const float*)d_in[5];
    const float* serev = (const float*)d_in[6];
    const float* w     = (const float*)d_in[7];
    const float* mu    = (const float*)d_in[8];
    const float* sig   = (const float*)d_in[9];
    const float* erev  = (const float*)d_in[10];
    const float* gleak = (const float*)d_in[11];
    const float* vleak = (const float*)d_in[12];
    const float* cm    = (const float*)d_in[13];
    const float* outw  = (const float*)d_in[14];
    const float* outb  = (const float*)d_in[15];
    const float* lnw   = (const float*)d_in[16];
    const float* lnb   = (const float*)d_in[17];
    const float* fcw   = (const float*)d_in[18];
    const float* fcb   = (const float*)d_in[19];
    float* out = (float*)d_out;

    const int n_syn = II * UU + UU * UU;           // 12288
    fold_params_kernel<<<(n_syn + 255) / 256, 256>>>(iw, ibv, sw, smu, ssig, serev,
                                                     w, mu, sig, erev);
    fold_neuron_kernel<<<1, 256>>>(gleak, vleak, cm);

    int nblocks = (BB * TT) / ROWS_PER_BLOCK;      // 2048
    sensory_kernel<<<nblocks, 512>>>(x);

    scan_kernel<<<BB / 2, 128>>>(outw, outb, lnw, lnb, fcw, fcb, out);
}